// round 9
// baseline (speedup 1.0000x reference)
#include <cuda_runtime.h>

// SmoothLDDTLoss, b=2, n=4096. Upper-triangle only (lddt = sum/count is
// invariant under halving both). Single fused kernel.
// All coordinates pre-scaled by 32 (= LUT segments per unit distance), so
// d32 = |td-pd| indexes the eps LUT directly and the cutoff compares are
// in scaled units (15->480, 30->960).

#define NPTS   4096
#define NB     2
#define ITILE  256
#define JTILE  64
#define NTILES 544                 // sum_{ti=0..15} (64 - 4*ti)
#define TOTAL_BLKS (NTILES * NB)

#define NSEG   512                 // d in [0,16), segment width 1/32
#define CSCALE 32.0f

__device__ float g_psum[NB][NTILES];
__device__ float g_pcnt[NB][NTILES];
__device__ unsigned int g_ticket = 0;

__device__ __forceinline__ float sigf(float z) {
    return 1.0f / (1.0f + __expf(-z));
}
__device__ __forceinline__ float eps_exact(float d) {
    return 0.25f * (sigf(0.5f - d) + sigf(1.0f - d) +
                    sigf(2.0f - d) + sigf(4.0f - d));
}

template<bool DIAG>
__device__ __forceinline__ void pair_loop(
    const float4* __restrict__ shP, const float4* __restrict__ shT,
    const float2* __restrict__ lut,
    float pxi, float pyi, float pzi,
    float txi, float tyi, float tzi,
    float ni480, int thresh, float& sum, float& cnt)
{
    #pragma unroll 8
    for (int jj = 0; jj < JTILE; ++jj) {
        const float4 P = shP[jj];   // 32*px, 32*py, 32*pz, nj(0/1)
        const float4 T = shT[jj];   // 32*tx, 32*ty, 32*tz, 0

        const float dx = pxi - P.x, dy = pyi - P.y, dz = pzi - P.z;
        const float pd2 = fmaf(dx, dx, fmaf(dy, dy, fmaf(dz, dz, 1.024e-9f)));
        const float ex = txi - T.x, ey = tyi - T.y, ez = tzi - T.z;
        const float td2 = fmaf(ex, ex, fmaf(ey, ey, fmaf(ez, ez, 1.024e-9f)));

        const float pd = pd2 * rsqrtf(pd2);     // 32 * true distance
        const float td = td2 * rsqrtf(td2);

        // d in LUT units, clamped into the table (|.| folds as src modifier)
        const float dc = fminf(fabsf(td - pd), 511.5f);
        const int   idx = __float2int_rz(dc);
        const float2 ab = lut[idx];
        const float eps = fmaf(ab.y, dc, ab.x);

        const float cs = fmaf(P.w, ni480, 480.0f);   // 480 or 960 (scaled)
        bool ok = td < cs;
        if (DIAG) ok = ok && (jj > thresh);

        const float m = ok ? 1.0f : 0.0f;            // FSEL, no branch
        sum = fmaf(eps, m, sum);
        cnt += m;
    }
}

__global__ __launch_bounds__(256) void lddt_fused_kernel(
    const float* __restrict__ pred,
    const float* __restrict__ truec,
    const unsigned char* __restrict__ dna,
    const unsigned char* __restrict__ rna,
    float* __restrict__ out)
{
    __shared__ float2 lut[NSEG];       // 4 KB
    __shared__ float4 shP[JTILE];      // 1 KB
    __shared__ float4 shT[JTILE];      // 1 KB
    __shared__ float red[256], redc[256];
    __shared__ float lddt_sh[NB];
    __shared__ unsigned int amLast;

    const int b    = blockIdx.y;
    const int tlin = blockIdx.x;
    const int t    = threadIdx.x;

    // eps LUT in d32 units: segment k covers d32 in [k, k+1).
    for (int k = t; k < NSEG; k += 256) {
        const float f0 = eps_exact((float)k * (1.0f / CSCALE));
        const float f1 = eps_exact((float)(k + 1) * (1.0f / CSCALE));
        const float bs = (k == NSEG - 1) ? 0.0f : (f1 - f0);   // per d32 unit
        lut[k] = make_float2(fmaf(-bs, (float)k, f0), bs);
    }

    // Decode linear tile id -> (ti, tj); cum(ti) = 2*ti*(33-ti).
    int ti = (int)((33.0f - sqrtf((float)(1089 - 2 * tlin))) * 0.5f);
    if (ti > 15) ti = 15;
    if (ti < 0)  ti = 0;
    while (ti > 0 && 2 * ti * (33 - ti) > tlin) --ti;
    while (2 * (ti + 1) * (32 - ti) <= tlin) ++ti;
    const int tj = 4 * ti + (tlin - 2 * ti * (33 - ti));

    const int i0 = ti * ITILE;
    const int j0 = tj * JTILE;

    // Stage the j tile (coords pre-scaled by 32).
    if (t < JTILE) {
        const int j = j0 + t;
        const float* pp = pred  + ((size_t)b * NPTS + j) * 3;
        const float* tp = truec + ((size_t)b * NPTS + j) * 3;
        const float nj = (dna[b * NPTS + j] | rna[b * NPTS + j]) ? 1.0f : 0.0f;
        shP[t] = make_float4(pp[0] * CSCALE, pp[1] * CSCALE, pp[2] * CSCALE, nj);
        shT[t] = make_float4(tp[0] * CSCALE, tp[1] * CSCALE, tp[2] * CSCALE, 0.0f);
    }

    // This thread's i point (scaled).
    const int i = i0 + t;
    const float* pp = pred  + ((size_t)b * NPTS + i) * 3;
    const float* tp = truec + ((size_t)b * NPTS + i) * 3;
    const float pxi = pp[0] * CSCALE, pyi = pp[1] * CSCALE, pzi = pp[2] * CSCALE;
    const float txi = tp[0] * CSCALE, tyi = tp[1] * CSCALE, tzi = tp[2] * CSCALE;
    const float ni480 = (dna[b * NPTS + i] | rna[b * NPTS + i]) ? 480.0f : 0.0f;
    const int thresh = i - j0;   // diag tiles: need jj > thresh

    __syncthreads();

    float sum = 0.0f, cnt = 0.0f;
    if (tj >= 4 * ti + 4) {
        pair_loop<false>(shP, shT, lut, pxi, pyi, pzi, txi, tyi, tzi,
                         ni480, thresh, sum, cnt);
    } else {
        pair_loop<true>(shP, shT, lut, pxi, pyi, pzi, txi, tyi, tzi,
                        ni480, thresh, sum, cnt);
    }

    // Block reduction (counts exact: integers < 2^24).
    red[t] = sum; redc[t] = cnt;
    __syncthreads();
    #pragma unroll
    for (int s = 128; s > 0; s >>= 1) {
        if (t < s) { red[t] += red[t + s]; redc[t] += redc[t + s]; }
        __syncthreads();
    }

    if (t == 0) {
        g_psum[b][tlin] = red[0];
        g_pcnt[b][tlin] = redc[0];
        __threadfence();
        const unsigned int old = atomicAdd(&g_ticket, 1u);
        amLast = (old == TOTAL_BLKS - 1) ? 1u : 0u;
    }
    __syncthreads();

    if (amLast) {
        // Deterministic fixed-order final reduction over all partials.
        for (int bb = 0; bb < NB; ++bb) {
            float s = 0.0f, c = 0.0f;
            for (int p = t; p < NTILES; p += 256) {
                s += g_psum[bb][p];
                c += g_pcnt[bb][p];
            }
            red[t] = s; redc[t] = c;
            __syncthreads();
            #pragma unroll
            for (int k = 128; k > 0; k >>= 1) {
                if (t < k) { red[t] += red[t + k]; redc[t] += redc[t + k]; }
                __syncthreads();
            }
            if (t == 0) lddt_sh[bb] = red[0] / fmaxf(redc[0], 1.0f);
            __syncthreads();
        }
        if (t == 0) {
            out[0] = 1.0f - 0.5f * (lddt_sh[0] + lddt_sh[1]);
            g_ticket = 0;   // reset for next graph replay
        }
    }
}

extern "C" void kernel_launch(void* const* d_in, const int* in_sizes, int n_in,
                              void* d_out, int out_size)
{
    const float*         pred  = (const float*)d_in[0];
    const float*         truec = (const float*)d_in[1];
    const unsigned char* dna   = (const unsigned char*)d_in[2];
    const unsigned char* rna   = (const unsigned char*)d_in[3];

    dim3 grid(NTILES, NB);
    lddt_fused_kernel<<<grid, 256>>>(pred, truec, dna, rna, (float*)d_out);
}

// round 11
// speedup vs baseline: 1.0739x; 1.0739x over previous
#include <cuda_runtime.h>

// SmoothLDDTLoss, b=2, n=4096. Upper-triangle only. Single fused kernel.
// Coords pre-scaled by 32 (LUT units). eps LUT stores (a+128, b) so ONE
// accumulator carries 128*count + sum; split per-thread after the loop.
// f32x2 packed math runs the pred/true distance chains in lane pairs.
// __launch_bounds__(256,8) forces <=32 regs -> 8 blocks/SM -> single wave.

#define NPTS   4096
#define NB     2
#define ITILE  256
#define JTILE  64
#define NTILES 544                 // sum_{ti=0..15} (64 - 4*ti)
#define TOTAL_BLKS (NTILES * NB)

#define NSEG   512                 // d32 in [0,512), width 1 unit = 1/32 A
#define CSCALE 32.0f

typedef unsigned long long ull;

__device__ float g_psum[NB][NTILES];
__device__ float g_pcnt[NB][NTILES];
__device__ unsigned int g_ticket = 0;

__device__ __forceinline__ ull pk2(float lo, float hi) {
    ull r; asm("mov.b64 %0,{%1,%2};" : "=l"(r) : "f"(lo), "f"(hi)); return r;
}
__device__ __forceinline__ void upk2(float& lo, float& hi, ull v) {
    asm("mov.b64 {%0,%1},%2;" : "=f"(lo), "=f"(hi) : "l"(v));
}
__device__ __forceinline__ ull fma2(ull a, ull b, ull c) {
    ull d; asm("fma.rn.f32x2 %0,%1,%2,%3;" : "=l"(d) : "l"(a), "l"(b), "l"(c)); return d;
}
__device__ __forceinline__ ull add2(ull a, ull b) {
    ull d; asm("add.rn.f32x2 %0,%1,%2;" : "=l"(d) : "l"(a), "l"(b)); return d;
}

__device__ __forceinline__ float sigf(float z) {
    return 1.0f / (1.0f + __expf(-z));
}
__device__ __forceinline__ float eps_exact(float d) {
    return 0.25f * (sigf(0.5f - d) + sigf(1.0f - d) +
                    sigf(2.0f - d) + sigf(4.0f - d));
}

template<bool DIAG>
__device__ __forceinline__ void pair_loop(
    const float4* __restrict__ sh0, const float4* __restrict__ sh1,
    const float2* __restrict__ lut,
    ull ix, ull iy, ull iz,
    float ni480, int thresh, float& acc)
{
    const ull EPS2 = pk2(1.024e-9f, 1.024e-9f);   // 1e-12 * 32^2, both lanes

    #pragma unroll 8
    for (int jj = 0; jj < JTILE; ++jj) {
        const float4 A = sh0[jj];   // (-32px, -32tx, -32py, -32ty)
        const float4 B = sh1[jj];   // (-32pz, -32tz, nj, 0)

        // packed (pred|true) difference + squared-norm chains
        const ull dx = add2(ix, pk2(A.x, A.y));
        const ull dy = add2(iy, pk2(A.z, A.w));
        const ull dz = add2(iz, pk2(B.x, B.y));
        ull q = fma2(dx, dx, EPS2);
        q = fma2(dy, dy, q);
        q = fma2(dz, dz, q);

        float pd2, td2;
        upk2(pd2, td2, q);
        const float pd = pd2 * rsqrtf(pd2);   // 32 * distances
        const float td = td2 * rsqrtf(td2);

        const float dc = fminf(fabsf(td - pd), 511.5f);
        const int idx = __float2int_rz(dc);
        const float2 ab = lut[idx];
        const float epsP = fmaf(ab.y, dc, ab.x);      // 128 + eps(d)

        const float cs = fmaf(B.z, ni480, 480.0f);    // 480 or 960
        bool ok = td < cs;
        if (DIAG) ok = ok && (jj > thresh);
        const float m = ok ? 1.0f : 0.0f;
        acc = fmaf(m, epsP, acc);                     // acc = 128*cnt + sum
    }
}

__global__ __launch_bounds__(256, 8) void lddt_fused_kernel(
    const float* __restrict__ pred,
    const float* __restrict__ truec,
    const unsigned char* __restrict__ dna,
    const unsigned char* __restrict__ rna,
    float* __restrict__ out)
{
    __shared__ float2 lut[NSEG];       // 4 KB
    __shared__ float4 sh0[JTILE];      // 1 KB
    __shared__ float4 sh1[JTILE];      // 1 KB
    __shared__ float red[256], redc[256];
    __shared__ float lddt_sh[NB];
    __shared__ unsigned int amLast;

    const int b    = blockIdx.y;
    const int tlin = blockIdx.x;
    const int t    = threadIdx.x;

    // eps LUT over d32 in [k, k+1); stores (a + 128, slope).
    for (int k = t; k < NSEG; k += 256) {
        const float f0 = eps_exact((float)k * (1.0f / CSCALE));
        const float f1 = eps_exact((float)(k + 1) * (1.0f / CSCALE));
        const float bs = (k == NSEG - 1) ? 0.0f : (f1 - f0);
        lut[k] = make_float2(fmaf(-bs, (float)k, f0) + 128.0f, bs);
    }

    // Decode linear tile id -> (ti, tj); cum(ti) = 2*ti*(33-ti).
    int ti = (int)((33.0f - sqrtf((float)(1089 - 2 * tlin))) * 0.5f);
    if (ti > 15) ti = 15;
    if (ti < 0)  ti = 0;
    while (ti > 0 && 2 * ti * (33 - ti) > tlin) --ti;
    while (2 * (ti + 1) * (32 - ti) <= tlin) ++ti;
    const int tj = 4 * ti + (tlin - 2 * ti * (33 - ti));

    const int i0 = ti * ITILE;
    const int j0 = tj * JTILE;

    // Stage the j tile: negated, scaled, (pred|true) interleaved.
    if (t < JTILE) {
        const int j = j0 + t;
        const float* pp = pred  + ((size_t)b * NPTS + j) * 3;
        const float* tp = truec + ((size_t)b * NPTS + j) * 3;
        const float nj = (dna[b * NPTS + j] | rna[b * NPTS + j]) ? 1.0f : 0.0f;
        sh0[t] = make_float4(-pp[0] * CSCALE, -tp[0] * CSCALE,
                             -pp[1] * CSCALE, -tp[1] * CSCALE);
        sh1[t] = make_float4(-pp[2] * CSCALE, -tp[2] * CSCALE, nj, 0.0f);
    }

    // This thread's i point, packed (pred|true) per component.
    const int i = i0 + t;
    const float* pp = pred  + ((size_t)b * NPTS + i) * 3;
    const float* tp = truec + ((size_t)b * NPTS + i) * 3;
    const ull ix = pk2(pp[0] * CSCALE, tp[0] * CSCALE);
    const ull iy = pk2(pp[1] * CSCALE, tp[1] * CSCALE);
    const ull iz = pk2(pp[2] * CSCALE, tp[2] * CSCALE);
    const float ni480 = (dna[b * NPTS + i] | rna[b * NPTS + i]) ? 480.0f : 0.0f;
    const int thresh = i - j0;   // diag tiles: need jj > thresh

    __syncthreads();

    float acc = 0.0f;
    if (tj >= 4 * ti + 4) {
        pair_loop<false>(sh0, sh1, lut, ix, iy, iz, ni480, thresh, acc);
    } else {
        pair_loop<true>(sh0, sh1, lut, ix, iy, iz, ni480, thresh, acc);
    }

    // Split acc = 128*cnt + sum (cnt <= 64, sum < 64).
    const float cnt = truncf(acc * 0.0078125f);
    const float sum = fmaf(cnt, -128.0f, acc);

    // Block reduction (counts exact: integers < 2^24).
    red[t] = sum; redc[t] = cnt;
    __syncthreads();
    #pragma unroll
    for (int s = 128; s > 0; s >>= 1) {
        if (t < s) { red[t] += red[t + s]; redc[t] += redc[t + s]; }
        __syncthreads();
    }

    if (t == 0) {
        g_psum[b][tlin] = red[0];
        g_pcnt[b][tlin] = redc[0];
        __threadfence();
        const unsigned int old = atomicAdd(&g_ticket, 1u);
        amLast = (old == TOTAL_BLKS - 1) ? 1u : 0u;
    }
    __syncthreads();

    if (amLast) {
        // Deterministic fixed-order final reduction over all partials.
        for (int bb = 0; bb < NB; ++bb) {
            float s = 0.0f, c = 0.0f;
            for (int p = t; p < NTILES; p += 256) {
                s += g_psum[bb][p];
                c += g_pcnt[bb][p];
            }
            red[t] = s; redc[t] = c;
            __syncthreads();
            #pragma unroll
            for (int k = 128; k > 0; k >>= 1) {
                if (t < k) { red[t] += red[t + k]; redc[t] += redc[t + k]; }
                __syncthreads();
            }
            if (t == 0) lddt_sh[bb] = red[0] / fmaxf(redc[0], 1.0f);
            __syncthreads();
        }
        if (t == 0) {
            out[0] = 1.0f - 0.5f * (lddt_sh[0] + lddt_sh[1]);
            g_ticket = 0;   // reset for next graph replay
        }
    }
}

extern "C" void kernel_launch(void* const* d_in, const int* in_sizes, int n_in,
                              void* d_out, int out_size)
{
    const float*         pred  = (const float*)d_in[0];
    const float*         truec = (const float*)d_in[1];
    const unsigned char* dna   = (const unsigned char*)d_in[2];
    const unsigned char* rna   = (const unsigned char*)d_in[3];

    dim3 grid(NTILES, NB);
    lddt_fused_kernel<<<grid, 256>>>(pred, truec, dna, rna, (float*)d_out);
}

// round 12
// speedup vs baseline: 1.1220x; 1.0447x over previous
#include <cuda_runtime.h>

// SmoothLDDTLoss, b=2, n=4096. Upper-triangle only. Single fused kernel.
// Coords pre-scaled by 64 (LUT units). 1024-entry nearest-sample eps LUT
// (midpoint-sampled, stores 128+eps so ONE accumulator carries
// 128*count + sum). J-tile stored PRE-PACKED as f32x2 pairs so the inner
// loop has zero pack/unpack MOVs on the j side.

#define NPTS   4096
#define NB     2
#define ITILE  256
#define JTILE  64
#define NTILES 544                 // sum_{ti=0..15} (64 - 4*ti)
#define TOTAL_BLKS (NTILES * NB)

#define NSEG   1024                // d64 in [0,1024): 16 A range
#define CSCALE 64.0f

typedef unsigned long long ull;

__device__ float g_psum[NB][NTILES];
__device__ float g_pcnt[NB][NTILES];
__device__ unsigned int g_ticket = 0;

__device__ __forceinline__ ull pk2(float lo, float hi) {
    ull r; asm("mov.b64 %0,{%1,%2};" : "=l"(r) : "f"(lo), "f"(hi)); return r;
}
__device__ __forceinline__ void upk2(float& lo, float& hi, ull v) {
    asm("mov.b64 {%0,%1},%2;" : "=f"(lo), "=f"(hi) : "l"(v));
}
__device__ __forceinline__ ull fma2(ull a, ull b, ull c) {
    ull d; asm("fma.rn.f32x2 %0,%1,%2,%3;" : "=l"(d) : "l"(a), "l"(b), "l"(c)); return d;
}
__device__ __forceinline__ ull add2(ull a, ull b) {
    ull d; asm("add.rn.f32x2 %0,%1,%2;" : "=l"(d) : "l"(a), "l"(b)); return d;
}

__device__ __forceinline__ float sigf(float z) {
    return 1.0f / (1.0f + __expf(-z));
}
__device__ __forceinline__ float eps_exact(float d) {
    return 0.25f * (sigf(0.5f - d) + sigf(1.0f - d) +
                    sigf(2.0f - d) + sigf(4.0f - d));
}

template<bool DIAG>
__device__ __forceinline__ void pair_loop(
    const ulonglong2* __restrict__ shXY,   // (-64px,-64tx),(-64py,-64ty)
    const ull* __restrict__ shZ,           // (-64pz,-64tz)
    const float* __restrict__ shNJ,        // nj in {0,1}
    const float* __restrict__ lut,         // 128 + eps, midpoint samples
    ull ix, ull iy, ull iz,
    float ni960, int thresh, float& acc)
{
    const ull EPS2 = pk2(4.096e-9f, 4.096e-9f);   // 1e-12 * 64^2 both lanes

    #pragma unroll 8
    for (int jj = 0; jj < JTILE; ++jj) {
        const ulonglong2 A = shXY[jj];
        const ull        Z = shZ[jj];
        const float      nj = shNJ[jj];

        // packed (pred|true) difference + squared-norm chain
        const ull dx = add2(ix, A.x);
        const ull dy = add2(iy, A.y);
        const ull dz = add2(iz, Z);
        ull q = fma2(dx, dx, EPS2);
        q = fma2(dy, dy, q);
        q = fma2(dz, dz, q);

        float pd2, td2;
        upk2(pd2, td2, q);
        const float pd = pd2 * rsqrtf(pd2);   // 64 * distances
        const float td = td2 * rsqrtf(td2);

        const float dc = fminf(fabsf(td - pd), 1023.0f);
        const int idx = __float2int_rz(dc);
        const float epsP = lut[idx];                  // 128 + eps(d)

        const float cs = fmaf(nj, ni960, 960.0f);     // 960 or 1920 (scaled)
        bool ok = td < cs;
        if (DIAG) ok = ok && (jj > thresh);
        const float m = ok ? 1.0f : 0.0f;
        acc = fmaf(m, epsP, acc);                     // acc = 128*cnt + sum
    }
}

__global__ __launch_bounds__(256, 8) void lddt_fused_kernel(
    const float* __restrict__ pred,
    const float* __restrict__ truec,
    const unsigned char* __restrict__ dna,
    const unsigned char* __restrict__ rna,
    float* __restrict__ out)
{
    __shared__ float      lut[NSEG];       // 4 KB
    __shared__ ulonglong2 shXY[JTILE];     // 1 KB
    __shared__ ull        shZ[JTILE];      // 512 B
    __shared__ float      shNJ[JTILE];     // 256 B
    __shared__ float red[256], redc[256];
    __shared__ float lddt_sh[NB];
    __shared__ unsigned int amLast;

    const int b    = blockIdx.y;
    const int tlin = blockIdx.x;
    const int t    = threadIdx.x;

    // Nearest-sample eps LUT: entry k = eps at midpoint (k+0.5)/64, +128.
    for (int k = t; k < NSEG; k += 256) {
        lut[k] = 128.0f + eps_exact(((float)k + 0.5f) * (1.0f / CSCALE));
    }

    // Decode linear tile id -> (ti, tj); cum(ti) = 2*ti*(33-ti).
    int ti = (int)((33.0f - sqrtf((float)(1089 - 2 * tlin))) * 0.5f);
    if (ti > 15) ti = 15;
    if (ti < 0)  ti = 0;
    while (ti > 0 && 2 * ti * (33 - ti) > tlin) --ti;
    while (2 * (ti + 1) * (32 - ti) <= tlin) ++ti;
    const int tj = 4 * ti + (tlin - 2 * ti * (33 - ti));

    const int i0 = ti * ITILE;
    const int j0 = tj * JTILE;

    // Stage the j tile: negated, scaled by 64, (pred|true) pre-packed.
    if (t < JTILE) {
        const int j = j0 + t;
        const float* pp = pred  + ((size_t)b * NPTS + j) * 3;
        const float* tp = truec + ((size_t)b * NPTS + j) * 3;
        ulonglong2 xy;
        xy.x = pk2(-pp[0] * CSCALE, -tp[0] * CSCALE);
        xy.y = pk2(-pp[1] * CSCALE, -tp[1] * CSCALE);
        shXY[t] = xy;
        shZ[t]  = pk2(-pp[2] * CSCALE, -tp[2] * CSCALE);
        shNJ[t] = (dna[b * NPTS + j] | rna[b * NPTS + j]) ? 1.0f : 0.0f;
    }

    // This thread's i point, packed (pred|true) per component.
    const int i = i0 + t;
    const float* pp = pred  + ((size_t)b * NPTS + i) * 3;
    const float* tp = truec + ((size_t)b * NPTS + i) * 3;
    const ull ix = pk2(pp[0] * CSCALE, tp[0] * CSCALE);
    const ull iy = pk2(pp[1] * CSCALE, tp[1] * CSCALE);
    const ull iz = pk2(pp[2] * CSCALE, tp[2] * CSCALE);
    const float ni960 = (dna[b * NPTS + i] | rna[b * NPTS + i]) ? 960.0f : 0.0f;
    const int thresh = i - j0;   // diag tiles: need jj > thresh

    __syncthreads();

    float acc = 0.0f;
    if (tj >= 4 * ti + 4) {
        pair_loop<false>(shXY, shZ, shNJ, lut, ix, iy, iz, ni960, thresh, acc);
    } else {
        pair_loop<true>(shXY, shZ, shNJ, lut, ix, iy, iz, ni960, thresh, acc);
    }

    // Split acc = 128*cnt + sum (cnt <= 64, sum < 64).
    const float cnt = truncf(acc * 0.0078125f);
    const float sum = fmaf(cnt, -128.0f, acc);

    // Block reduction (counts exact: integers < 2^24).
    red[t] = sum; redc[t] = cnt;
    __syncthreads();
    #pragma unroll
    for (int s = 128; s > 0; s >>= 1) {
        if (t < s) { red[t] += red[t + s]; redc[t] += redc[t + s]; }
        __syncthreads();
    }

    if (t == 0) {
        g_psum[b][tlin] = red[0];
        g_pcnt[b][tlin] = redc[0];
        __threadfence();
        const unsigned int old = atomicAdd(&g_ticket, 1u);
        amLast = (old == TOTAL_BLKS - 1) ? 1u : 0u;
    }
    __syncthreads();

    if (amLast) {
        // Deterministic fixed-order final reduction over all partials.
        for (int bb = 0; bb < NB; ++bb) {
            float s = 0.0f, c = 0.0f;
            for (int p = t; p < NTILES; p += 256) {
                s += g_psum[bb][p];
                c += g_pcnt[bb][p];
            }
            red[t] = s; redc[t] = c;
            __syncthreads();
            #pragma unroll
            for (int k = 128; k > 0; k >>= 1) {
                if (t < k) { red[t] += red[t + k]; redc[t] += redc[t + k]; }
                __syncthreads();
            }
            if (t == 0) lddt_sh[bb] = red[0] / fmaxf(redc[0], 1.0f);
            __syncthreads();
        }
        if (t == 0) {
            out[0] = 1.0f - 0.5f * (lddt_sh[0] + lddt_sh[1]);
            g_ticket = 0;   // reset for next graph replay
        }
    }
}

extern "C" void kernel_launch(void* const* d_in, const int* in_sizes, int n_in,
                              void* d_out, int out_size)
{
    const float*         pred  = (const float*)d_in[0];
    const float*         truec = (const float*)d_in[1];
    const unsigned char* dna   = (const unsigned char*)d_in[2];
    const unsigned char* rna   = (const unsigned char*)d_in[3];

    dim3 grid(NTILES, NB);
    lddt_fused_kernel<<<grid, 256>>>(pred, truec, dna, rna, (float*)d_out);
}

// round 13
// speedup vs baseline: 1.2013x; 1.0707x over previous
#include <cuda_runtime.h>

// SmoothLDDTLoss, b=2, n=4096. Upper-triangle only. Single fused kernel.
// Coords pre-scaled by 64 (LUT units). 1024-entry nearest-sample eps LUT
// (midpoint-sampled; stores 128+eps so ONE accumulator carries
// 128*count + sum). J-tiles are PARTITIONED at staging (non-nucleic first,
// deterministic ballot ranks) so the inner loop runs two segments with
// constant cutoffs -- no per-pair nj load, no per-pair cutoff FFMA.
// Diag tiles keep the unsorted path (need original j for the j>i test).

#define NPTS   4096
#define NB     2
#define ITILE  256
#define JTILE  64
#define NTILES 544                 // sum_{ti=0..15} (64 - 4*ti)
#define TOTAL_BLKS (NTILES * NB)

#define NSEG   1024                // d64 in [0,1024): 16 A range
#define CSCALE 64.0f

typedef unsigned long long ull;

__device__ float g_psum[NB][NTILES];
__device__ float g_pcnt[NB][NTILES];
__device__ unsigned int g_ticket = 0;

__device__ __forceinline__ ull pk2(float lo, float hi) {
    ull r; asm("mov.b64 %0,{%1,%2};" : "=l"(r) : "f"(lo), "f"(hi)); return r;
}
__device__ __forceinline__ void upk2(float& lo, float& hi, ull v) {
    asm("mov.b64 {%0,%1},%2;" : "=f"(lo), "=f"(hi) : "l"(v));
}
__device__ __forceinline__ ull fma2(ull a, ull b, ull c) {
    ull d; asm("fma.rn.f32x2 %0,%1,%2,%3;" : "=l"(d) : "l"(a), "l"(b), "l"(c)); return d;
}
__device__ __forceinline__ ull add2(ull a, ull b) {
    ull d; asm("add.rn.f32x2 %0,%1,%2;" : "=l"(d) : "l"(a), "l"(b)); return d;
}
__device__ __forceinline__ float sqrt_a(float x) {
    float r; asm("sqrt.approx.f32 %0,%1;" : "=f"(r) : "f"(x)); return r;
}

__device__ __forceinline__ float sigf(float z) {
    return 1.0f / (1.0f + __expf(-z));
}
__device__ __forceinline__ float eps_exact(float d) {
    return 0.25f * (sigf(0.5f - d) + sigf(1.0f - d) +
                    sigf(2.0f - d) + sigf(4.0f - d));
}

// One pair: packed (pred|true) distance chain -> td, epsP.
#define PAIR_CORE(jj)                                                   \
    const ulonglong2 A = shXY[jj];                                      \
    const ull        Z = shZ[jj];                                       \
    const ull dxp = add2(ix, A.x);                                      \
    const ull dyp = add2(iy, A.y);                                      \
    const ull dzp = add2(iz, Z);                                        \
    ull q = fma2(dxp, dxp, EPS2);                                       \
    q = fma2(dyp, dyp, q);                                              \
    q = fma2(dzp, dzp, q);                                              \
    float pd2, td2; upk2(pd2, td2, q);                                  \
    const float pd = sqrt_a(pd2);                                       \
    const float td = sqrt_a(td2);                                       \
    const float dc = fminf(fabsf(td - pd), 1023.0f);                    \
    const float epsP = lut[__float2int_rz(dc)];

__global__ __launch_bounds__(256, 8) void lddt_fused_kernel(
    const float* __restrict__ pred,
    const float* __restrict__ truec,
    const unsigned char* __restrict__ dna,
    const unsigned char* __restrict__ rna,
    float* __restrict__ out)
{
    __shared__ float      lut[NSEG];       // 4 KB
    __shared__ ulonglong2 shXY[JTILE];     // 1 KB
    __shared__ ull        shZ[JTILE];      // 512 B
    __shared__ float      shNJ[JTILE];     // 256 B (diag tiles only)
    __shared__ float red[256], redc[256];
    __shared__ float lddt_sh[NB];
    __shared__ unsigned int amLast;
    __shared__ int sWarpNuc[2];
    __shared__ int sNNon;

    const int b    = blockIdx.y;
    const int tlin = blockIdx.x;
    const int t    = threadIdx.x;

    // Nearest-sample eps LUT: entry k = eps at midpoint (k+0.5)/64, +128.
    for (int k = t; k < NSEG; k += 256) {
        lut[k] = 128.0f + eps_exact(((float)k + 0.5f) * (1.0f / CSCALE));
    }

    // Decode linear tile id -> (ti, tj); cum(ti) = 2*ti*(33-ti).
    int ti = (int)((33.0f - sqrtf((float)(1089 - 2 * tlin))) * 0.5f);
    if (ti > 15) ti = 15;
    if (ti < 0)  ti = 0;
    while (ti > 0 && 2 * ti * (33 - ti) > tlin) --ti;
    while (2 * (ti + 1) * (32 - ti) <= tlin) ++ti;
    const int tj = 4 * ti + (tlin - 2 * ti * (33 - ti));
    const bool diag = (tj < 4 * ti + 4);

    const int i0 = ti * ITILE;
    const int j0 = tj * JTILE;

    // ---- Stage the j tile (partitioned for non-diag tiles) ----
    float jpx = 0, jpy = 0, jpz = 0, jtx = 0, jty = 0, jtz = 0;
    bool nuc = false;
    if (t < JTILE) {
        const int j = j0 + t;
        const float* pp = pred  + ((size_t)b * NPTS + j) * 3;
        const float* tp = truec + ((size_t)b * NPTS + j) * 3;
        jpx = pp[0]; jpy = pp[1]; jpz = pp[2];
        jtx = tp[0]; jty = tp[1]; jtz = tp[2];
        nuc = (dna[b * NPTS + j] | rna[b * NPTS + j]) != 0;
    }
    const unsigned bal = __ballot_sync(0xffffffffu, nuc);
    if (t < JTILE && (t & 31) == 0) sWarpNuc[t >> 5] = __popc(bal);
    __syncthreads();

    int pos = t;
    if (!diag && t < JTILE) {
        const int nNon = JTILE - sWarpNuc[0] - sWarpNuc[1];
        const int lt = __popc(bal & ((1u << (t & 31)) - 1u));
        pos = nuc ? (nNon + lt + ((t >= 32) ? sWarpNuc[0] : 0))
                  : ((t & 31) - lt + ((t >= 32) ? (32 - sWarpNuc[0]) : 0));
        if (t == 0) sNNon = nNon;
    }
    if (diag && t == 0) sNNon = 0;   // unused on diag path
    if (t < JTILE) {
        ulonglong2 xy;
        xy.x = pk2(-jpx * CSCALE, -jtx * CSCALE);
        xy.y = pk2(-jpy * CSCALE, -jty * CSCALE);
        shXY[pos] = xy;
        shZ[pos]  = pk2(-jpz * CSCALE, -jtz * CSCALE);
        shNJ[pos] = nuc ? 1.0f : 0.0f;
    }

    // ---- This thread's i point, packed (pred|true) per component ----
    const int i = i0 + t;
    const float* pp = pred  + ((size_t)b * NPTS + i) * 3;
    const float* tp = truec + ((size_t)b * NPTS + i) * 3;
    const ull ix = pk2(pp[0] * CSCALE, tp[0] * CSCALE);
    const ull iy = pk2(pp[1] * CSCALE, tp[1] * CSCALE);
    const ull iz = pk2(pp[2] * CSCALE, tp[2] * CSCALE);
    const bool inuc = (dna[b * NPTS + i] | rna[b * NPTS + i]) != 0;
    const float ni960 = inuc ? 960.0f : 0.0f;
    const float csn   = inuc ? 1920.0f : 960.0f;   // nuc-j segment cutoff
    const int thresh = i - j0;                     // diag: need jj > thresh

    __syncthreads();
    const int nNon = sNNon;
    const ull EPS2 = pk2(4.096e-9f, 4.096e-9f);    // 1e-12 * 64^2

    float acc = 0.0f;                              // acc = 128*cnt + sum
    if (!diag) {
        int jj = 0;
        #pragma unroll 4
        for (; jj < nNon; ++jj) {                  // non-nucleic j: cutoff 15A
            PAIR_CORE(jj)
            if (td < 960.0f) acc += epsP;
        }
        #pragma unroll 4
        for (; jj < JTILE; ++jj) {                 // nucleic j: cutoff 15/30
            PAIR_CORE(jj)
            if (td < csn) acc += epsP;
        }
    } else {
        #pragma unroll 8
        for (int jj = 0; jj < JTILE; ++jj) {
            PAIR_CORE(jj)
            const float nj = shNJ[jj];
            const float cs = fmaf(nj, ni960, 960.0f);
            if ((td < cs) && (jj > thresh)) acc += epsP;
        }
    }

    // Split acc = 128*cnt + sum (cnt <= 64, sum < 64).
    const float cnt = truncf(acc * 0.0078125f);
    const float sum = fmaf(cnt, -128.0f, acc);

    // Block reduction (counts exact: integers < 2^24).
    red[t] = sum; redc[t] = cnt;
    __syncthreads();
    #pragma unroll
    for (int s = 128; s > 0; s >>= 1) {
        if (t < s) { red[t] += red[t + s]; redc[t] += redc[t + s]; }
        __syncthreads();
    }

    if (t == 0) {
        g_psum[b][tlin] = red[0];
        g_pcnt[b][tlin] = redc[0];
        __threadfence();
        const unsigned int old = atomicAdd(&g_ticket, 1u);
        amLast = (old == TOTAL_BLKS - 1) ? 1u : 0u;
    }
    __syncthreads();

    if (amLast) {
        // Deterministic finalize: half-block per batch, fixed order.
        const int bb = t >> 7;        // 0 or 1
        const int l  = t & 127;
        float s = 0.0f, c = 0.0f;
        for (int p = l; p < NTILES; p += 128) {
            s += g_psum[bb][p];
            c += g_pcnt[bb][p];
        }
        red[t] = s; redc[t] = c;
        __syncthreads();
        #pragma unroll
        for (int k = 64; k > 0; k >>= 1) {
            if (l < k) { red[t] += red[t + k]; redc[t] += redc[t + k]; }
            __syncthreads();
        }
        if (l == 0) lddt_sh[bb] = red[t] / fmaxf(redc[t], 1.0f);
        __syncthreads();
        if (t == 0) {
            out[0] = 1.0f - 0.5f * (lddt_sh[0] + lddt_sh[1]);
            g_ticket = 0;   // reset for next graph replay
        }
    }
}

extern "C" void kernel_launch(void* const* d_in, const int* in_sizes, int n_in,
                              void* d_out, int out_size)
{
    const float*         pred  = (const float*)d_in[0];
    const float*         truec = (const float*)d_in[1];
    const unsigned char* dna   = (const unsigned char*)d_in[2];
    const unsigned char* rna   = (const unsigned char*)d_in[3];

    dim3 grid(NTILES, NB);
    lddt_fused_kernel<<<grid, 256>>>(pred, truec, dna, rna, (float*)d_out);
}

// round 14
// speedup vs baseline: 1.3382x; 1.1139x over previous
#include <cuda_runtime.h>

// SmoothLDDTLoss, b=2, n=4096. Upper-triangle only. Single fused kernel.
// Register blocking: each thread owns TWO i-points (i0+t, i0+256+t) so every
// j-tile LDS + loop iteration feeds two pairs. Coords pre-scaled by 64.
// 1024-entry nearest-sample eps LUT (midpoint; stores 128+eps so one
// accumulator per i-point carries 128*count + sum). J-tiles partitioned
// (non-nucleic first, deterministic ballot ranks) -> constant cutoffs in
// the inner loops. Diag tiles keep original j order for the j>i test.

#define NPTS   4096
#define NB     2
#define ITILE  512
#define JTILE  64
#define NTILES 288                 // sum_{ti=0..7} (64 - 8*ti)
#define TOTAL_BLKS (NTILES * NB)

#define NSEG   1024                // d64 in [0,1024): 16 A range
#define CSCALE 64.0f

typedef unsigned long long ull;

__device__ float g_psum[NB][NTILES];
__device__ float g_pcnt[NB][NTILES];
__device__ unsigned int g_ticket = 0;

__device__ __forceinline__ ull pk2(float lo, float hi) {
    ull r; asm("mov.b64 %0,{%1,%2};" : "=l"(r) : "f"(lo), "f"(hi)); return r;
}
__device__ __forceinline__ void upk2(float& lo, float& hi, ull v) {
    asm("mov.b64 {%0,%1},%2;" : "=f"(lo), "=f"(hi) : "l"(v));
}
__device__ __forceinline__ ull fma2(ull a, ull b, ull c) {
    ull d; asm("fma.rn.f32x2 %0,%1,%2,%3;" : "=l"(d) : "l"(a), "l"(b), "l"(c)); return d;
}
__device__ __forceinline__ ull add2(ull a, ull b) {
    ull d; asm("add.rn.f32x2 %0,%1,%2;" : "=l"(d) : "l"(a), "l"(b)); return d;
}
__device__ __forceinline__ float sqrt_a(float x) {
    float r; asm("sqrt.approx.f32 %0,%1;" : "=f"(r) : "f"(x)); return r;
}

__device__ __forceinline__ float sigf(float z) {
    return 1.0f / (1.0f + __expf(-z));
}
__device__ __forceinline__ float eps_exact(float d) {
    return 0.25f * (sigf(0.5f - d) + sigf(1.0f - d) +
                    sigf(2.0f - d) + sigf(4.0f - d));
}

// One pair: packed (pred|true) distance chain -> td and 128+eps(d).
__device__ __forceinline__ void pair_eval(
    const ulonglong2 A, const ull Z, const ull EPS2,
    ull ix, ull iy, ull iz, const float* __restrict__ lut,
    float& td, float& epsP)
{
    const ull dx = add2(ix, A.x);
    const ull dy = add2(iy, A.y);
    const ull dz = add2(iz, Z);
    ull q = fma2(dx, dx, EPS2);
    q = fma2(dy, dy, q);
    q = fma2(dz, dz, q);
    float pd2, td2; upk2(pd2, td2, q);
    const float pd = sqrt_a(pd2);
    td = sqrt_a(td2);
    const float dc = fminf(fabsf(td - pd), 1023.0f);
    epsP = lut[__float2int_rz(dc)];
}

__global__ __launch_bounds__(256, 4) void lddt_fused_kernel(
    const float* __restrict__ pred,
    const float* __restrict__ truec,
    const unsigned char* __restrict__ dna,
    const unsigned char* __restrict__ rna,
    float* __restrict__ out)
{
    __shared__ float      lut[NSEG];       // 4 KB
    __shared__ ulonglong2 shXY[JTILE];     // 1 KB
    __shared__ ull        shZ[JTILE];      // 512 B
    __shared__ float      shNJ[JTILE];     // diag tiles only
    __shared__ float red[256], redc[256];
    __shared__ float lddt_sh[NB];
    __shared__ unsigned int amLast;
    __shared__ int sWarpNuc[2];
    __shared__ int sNNon;

    const int b    = blockIdx.y;
    const int tlin = blockIdx.x;
    const int t    = threadIdx.x;

    // Nearest-sample eps LUT: entry k = eps at midpoint (k+0.5)/64, +128.
    for (int k = t; k < NSEG; k += 256) {
        lut[k] = 128.0f + eps_exact(((float)k + 0.5f) * (1.0f / CSCALE));
    }

    // Decode linear tile id -> (ti, tj); cum(ti) = 4*ti*(17-ti).
    int ti = (int)((17.0f - sqrtf((float)(289 - tlin))) * 0.5f);
    if (ti > 7) ti = 7;
    if (ti < 0) ti = 0;
    while (ti > 0 && 4 * ti * (17 - ti) > tlin) --ti;
    while (4 * (ti + 1) * (16 - ti) <= tlin) ++ti;
    const int tj = 8 * ti + (tlin - 4 * ti * (17 - ti));
    const bool diag = (tj < 8 * ti + 8);

    const int i0 = ti * ITILE;
    const int j0 = tj * JTILE;

    // ---- Stage the j tile (partitioned for non-diag tiles) ----
    float jpx = 0, jpy = 0, jpz = 0, jtx = 0, jty = 0, jtz = 0;
    bool nuc = false;
    if (t < JTILE) {
        const int j = j0 + t;
        const float* pp = pred  + ((size_t)b * NPTS + j) * 3;
        const float* tp = truec + ((size_t)b * NPTS + j) * 3;
        jpx = pp[0]; jpy = pp[1]; jpz = pp[2];
        jtx = tp[0]; jty = tp[1]; jtz = tp[2];
        nuc = (dna[b * NPTS + j] | rna[b * NPTS + j]) != 0;
    }
    const unsigned bal = __ballot_sync(0xffffffffu, nuc);
    if (t < JTILE && (t & 31) == 0) sWarpNuc[t >> 5] = __popc(bal);
    __syncthreads();

    int pos = t;
    if (!diag && t < JTILE) {
        const int nNon = JTILE - sWarpNuc[0] - sWarpNuc[1];
        const int lt = __popc(bal & ((1u << (t & 31)) - 1u));
        pos = nuc ? (nNon + lt + ((t >= 32) ? sWarpNuc[0] : 0))
                  : ((t & 31) - lt + ((t >= 32) ? (32 - sWarpNuc[0]) : 0));
        if (t == 0) sNNon = nNon;
    }
    if (diag && t == 0) sNNon = 0;
    if (t < JTILE) {
        ulonglong2 xy;
        xy.x = pk2(-jpx * CSCALE, -jtx * CSCALE);
        xy.y = pk2(-jpy * CSCALE, -jty * CSCALE);
        shXY[pos] = xy;
        shZ[pos]  = pk2(-jpz * CSCALE, -jtz * CSCALE);
        shNJ[pos] = nuc ? 1.0f : 0.0f;
    }

    // ---- This thread's TWO i points, packed (pred|true) per component ----
    const int i1 = i0 + t;
    const int i2 = i0 + 256 + t;
    const float* pp1 = pred  + ((size_t)b * NPTS + i1) * 3;
    const float* tp1 = truec + ((size_t)b * NPTS + i1) * 3;
    const float* pp2 = pred  + ((size_t)b * NPTS + i2) * 3;
    const float* tp2 = truec + ((size_t)b * NPTS + i2) * 3;
    const ull ix1 = pk2(pp1[0] * CSCALE, tp1[0] * CSCALE);
    const ull iy1 = pk2(pp1[1] * CSCALE, tp1[1] * CSCALE);
    const ull iz1 = pk2(pp1[2] * CSCALE, tp1[2] * CSCALE);
    const ull ix2 = pk2(pp2[0] * CSCALE, tp2[0] * CSCALE);
    const ull iy2 = pk2(pp2[1] * CSCALE, tp2[1] * CSCALE);
    const ull iz2 = pk2(pp2[2] * CSCALE, tp2[2] * CSCALE);
    const bool inuc1 = (dna[b * NPTS + i1] | rna[b * NPTS + i1]) != 0;
    const bool inuc2 = (dna[b * NPTS + i2] | rna[b * NPTS + i2]) != 0;
    const float ni960_1 = inuc1 ? 960.0f : 0.0f;
    const float ni960_2 = inuc2 ? 960.0f : 0.0f;
    const float csn1 = inuc1 ? 1920.0f : 960.0f;
    const float csn2 = inuc2 ? 1920.0f : 960.0f;
    const int thresh1 = i1 - j0;
    const int thresh2 = i2 - j0;

    __syncthreads();
    const int nNon = sNNon;
    const ull EPS2 = pk2(4.096e-9f, 4.096e-9f);    // 1e-12 * 64^2

    float acc1 = 0.0f, acc2 = 0.0f;                // 128*cnt + sum each
    if (!diag) {
        int jj = 0;
        #pragma unroll 4
        for (; jj < nNon; ++jj) {                  // non-nucleic j: 15A
            const ulonglong2 A = shXY[jj];
            const ull        Z = shZ[jj];
            float td1, e1, td2, e2;
            pair_eval(A, Z, EPS2, ix1, iy1, iz1, lut, td1, e1);
            pair_eval(A, Z, EPS2, ix2, iy2, iz2, lut, td2, e2);
            if (td1 < 960.0f) acc1 += e1;
            if (td2 < 960.0f) acc2 += e2;
        }
        #pragma unroll 4
        for (; jj < JTILE; ++jj) {                 // nucleic j: 15/30A
            const ulonglong2 A = shXY[jj];
            const ull        Z = shZ[jj];
            float td1, e1, td2, e2;
            pair_eval(A, Z, EPS2, ix1, iy1, iz1, lut, td1, e1);
            pair_eval(A, Z, EPS2, ix2, iy2, iz2, lut, td2, e2);
            if (td1 < csn1) acc1 += e1;
            if (td2 < csn2) acc2 += e2;
        }
    } else {
        #pragma unroll 8
        for (int jj = 0; jj < JTILE; ++jj) {
            const ulonglong2 A = shXY[jj];
            const ull        Z = shZ[jj];
            const float      nj = shNJ[jj];
            float td1, e1, td2, e2;
            pair_eval(A, Z, EPS2, ix1, iy1, iz1, lut, td1, e1);
            pair_eval(A, Z, EPS2, ix2, iy2, iz2, lut, td2, e2);
            const float cs1 = fmaf(nj, ni960_1, 960.0f);
            const float cs2 = fmaf(nj, ni960_2, 960.0f);
            if ((td1 < cs1) && (jj > thresh1)) acc1 += e1;
            if ((td2 < cs2) && (jj > thresh2)) acc2 += e2;
        }
    }

    // Split acc = 128*cnt + sum per i-point (cnt <= 64, sum < 64 each).
    const float cnt1 = truncf(acc1 * 0.0078125f);
    const float cnt2 = truncf(acc2 * 0.0078125f);
    const float sum12 = fmaf(cnt1, -128.0f, acc1) + fmaf(cnt2, -128.0f, acc2);

    // Block reduction (counts exact: integers < 2^24).
    red[t] = sum12; redc[t] = cnt1 + cnt2;
    __syncthreads();
    #pragma unroll
    for (int s = 128; s > 0; s >>= 1) {
        if (t < s) { red[t] += red[t + s]; redc[t] += redc[t + s]; }
        __syncthreads();
    }

    if (t == 0) {
        g_psum[b][tlin] = red[0];
        g_pcnt[b][tlin] = redc[0];
        __threadfence();
        const unsigned int old = atomicAdd(&g_ticket, 1u);
        amLast = (old == TOTAL_BLKS - 1) ? 1u : 0u;
    }
    __syncthreads();

    if (amLast) {
        // Deterministic finalize: half-block per batch, fixed order.
        const int bb = t >> 7;        // 0 or 1
        const int l  = t & 127;
        float s = 0.0f, c = 0.0f;
        for (int p = l; p < NTILES; p += 128) {
            s += g_psum[bb][p];
            c += g_pcnt[bb][p];
        }
        red[t] = s; redc[t] = c;
        __syncthreads();
        #pragma unroll
        for (int k = 64; k > 0; k >>= 1) {
            if (l < k) { red[t] += red[t + k]; redc[t] += redc[t + k]; }
            __syncthreads();
        }
        if (l == 0) lddt_sh[bb] = red[t] / fmaxf(redc[t], 1.0f);
        __syncthreads();
        if (t == 0) {
            out[0] = 1.0f - 0.5f * (lddt_sh[0] + lddt_sh[1]);
            g_ticket = 0;   // reset for next graph replay
        }
    }
}

extern "C" void kernel_launch(void* const* d_in, const int* in_sizes, int n_in,
                              void* d_out, int out_size)
{
    const float*         pred  = (const float*)d_in[0];
    const float*         truec = (const float*)d_in[1];
    const unsigned char* dna   = (const unsigned char*)d_in[2];
    const unsigned char* rna   = (const unsigned char*)d_in[3];

    dim3 grid(NTILES, NB);
    lddt_fused_kernel<<<grid, 256>>>(pred, truec, dna, rna, (float*)d_out);
}